// round 4
// baseline (speedup 1.0000x reference)
#include <cuda_runtime.h>
#include <cstdint>

#define B_     32
#define H_     2048
#define V_     128000
#define HIST_  2048
#define KCH    256
#define VTILE  16
#define CAP    1024

// ---------------- device scratch (no allocation allowed) ----------------
__device__ float g_h[B_ * H_];                    // layernorm output, plain [b][k]
__device__ float g_logits[(size_t)B_ * V_];       // 16.4 MB
__device__ float g_pen[B_ * HIST_];

// ---------------- f32x2 helpers ----------------
__device__ __forceinline__ unsigned long long fma2(unsigned long long a,
                                                   unsigned long long b,
                                                   unsigned long long c) {
    unsigned long long d;
    asm("fma.rn.f32x2 %0, %1, %2, %3;" : "=l"(d) : "l"(a), "l"(b), "l"(c));
    return d;
}
__device__ __forceinline__ unsigned long long add2(unsigned long long a,
                                                   unsigned long long b) {
    unsigned long long d;
    asm("add.rn.f32x2 %0, %1, %2;" : "=l"(d) : "l"(a), "l"(b));
    return d;
}

// ---------------- K0: LayerNorm ----------------
__global__ void __launch_bounds__(256) ln_kernel(const float* __restrict__ hs,
                                                 const float* __restrict__ gamma,
                                                 const float* __restrict__ beta) {
    __shared__ float sbuf[8];
    const int b = blockIdx.x, tid = threadIdx.x;
    const float* x = hs + (size_t)b * H_;

    float v[8];
#pragma unroll
    for (int i = 0; i < 8; i++) v[i] = x[i * 256 + tid];

    float s = 0.f;
#pragma unroll
    for (int i = 0; i < 8; i++) s += v[i];
#pragma unroll
    for (int off = 16; off >= 1; off >>= 1) s += __shfl_xor_sync(0xffffffffu, s, off);
    if ((tid & 31) == 0) sbuf[tid >> 5] = s;
    __syncthreads();
    if (tid == 0) {
        float t = 0.f;
        for (int i = 0; i < 8; i++) t += sbuf[i];
        sbuf[0] = t * (1.0f / H_);
    }
    __syncthreads();
    const float mean = sbuf[0];
    __syncthreads();

    float sq = 0.f;
#pragma unroll
    for (int i = 0; i < 8; i++) { float d = v[i] - mean; sq += d * d; }
#pragma unroll
    for (int off = 16; off >= 1; off >>= 1) sq += __shfl_xor_sync(0xffffffffu, sq, off);
    if ((tid & 31) == 0) sbuf[tid >> 5] = sq;
    __syncthreads();
    if (tid == 0) {
        float t = 0.f;
        for (int i = 0; i < 8; i++) t += sbuf[i];
        sbuf[0] = t * (1.0f / H_);
    }
    __syncthreads();
    const float var = sbuf[0];
    const float rs = rsqrtf(var + 1e-5f);

#pragma unroll
    for (int i = 0; i < 8; i++) {
        const int k = i * 256 + tid;
        g_h[b * H_ + k] = (v[i] - mean) * rs * gamma[k] + beta[k];
    }
}

// ---------------- K1: fp32 GEMM, k-paired FFMA2, no operand duplication ----------------
// 256 threads = 8 warps = 4 b-groups (8 b each) x 2 v-groups (8 v each). VTILE=16.
__global__ void __launch_bounds__(256, 1) gemm_kernel(const float* __restrict__ W) {
    __shared__ __align__(16) float sh[B_ * KCH];     // h tile: [b][kk], 32 KB
    const int tid  = threadIdx.x;
    const int lane = tid & 31;
    const int wrp  = tid >> 5;
    const int bg   = wrp & 3;                        // b-group: b0 = bg*8
    const int vg   = wrp >> 2;                       // v-group: 8 rows
    const int b0   = bg * 8;
    const int v0   = blockIdx.x * VTILE + vg * 8;

    unsigned long long A[64];                        // acc[t], t = p*8+q (p: b, q: v)
#pragma unroll
    for (int t = 0; t < 64; t++) A[t] = 0ull;

    const unsigned long long* gh = reinterpret_cast<const unsigned long long*>(g_h);
    unsigned long long* shv = reinterpret_cast<unsigned long long*>(sh);

    for (int c = 0; c < H_; c += KCH) {
        __syncthreads();
        // fill h tile: 32 b x 128 u64 (k-pairs)
#pragma unroll
        for (int r = 0; r < 16; r++) {
            const int idx = tid + r * 256;           // 0..4095
            const int bb = idx >> 7;
            const int kk = idx & 127;
            shv[idx] = gh[bb * (H_ / 2) + (c >> 1) + kk];
        }
        __syncthreads();

#pragma unroll
        for (int j = 0; j < KCH / 64; j++) {
            const int klp = lane + j * 32;           // k-pair index within chunk

            unsigned long long hv[8];
#pragma unroll
            for (int p = 0; p < 8; p++)
                hv[p] = shv[(b0 + p) * (KCH / 2) + klp];

            const float* wp = W + (size_t)v0 * H_ + c + klp * 2;
            unsigned long long wv[8];
#pragma unroll
            for (int q = 0; q < 8; q++)
                wv[q] = *reinterpret_cast<const unsigned long long*>(wp + (size_t)q * H_);

#pragma unroll
            for (int q = 0; q < 8; q++)
#pragma unroll
                for (int p = 0; p < 8; p++)
                    A[p * 8 + q] = fma2(wv[q], hv[p], A[p * 8 + q]);
        }
    }

    // log-tree exchange reduction: 64 accs across 32 lanes -> 2 totals per lane
#pragma unroll
    for (int step = 0; step < 5; step++) {
        const int off = 16 >> step;
        const int n2  = 32 >> step;
        const bool up = (lane & off) != 0;
#pragma unroll
        for (int i = 0; i < 32; i++) {
            if (i >= n2) break;                      // unrolled: compile-time pruned
            const unsigned long long send = up ? A[i] : A[i + n2];
            const unsigned long long recv = __shfl_xor_sync(0xffffffffu, send, off);
            const unsigned long long keep = up ? A[i + n2] : A[i];
            A[i] = add2(keep, recv);
        }
    }

    // lane holds totals for t = 2*lane (A[0]) and t = 2*lane+1 (A[1])
#pragma unroll
    for (int i = 0; i < 2; i++) {
        const int t = 2 * lane + i;
        const int p = t >> 3, q = t & 7;
        const unsigned long long a = A[i];
        const float f = __uint_as_float((unsigned)(a & 0xffffffffu)) +
                        __uint_as_float((unsigned)(a >> 32));
        g_logits[(size_t)(b0 + p) * V_ + (v0 + q)] = f;
    }
}

// ---------------- P1/P2: repetition penalty (two-phase, race-free) ----------------
__global__ void __launch_bounds__(256) pen_gather(const int* __restrict__ ids) {
    const int t = blockIdx.x * 256 + threadIdx.x;
    if (t >= B_ * HIST_) return;
    const int b = t >> 11;
    const int v = ids[t];
    if ((unsigned)v >= (unsigned)V_) return;
    const float g = g_logits[(size_t)b * V_ + v];
    g_pen[t] = (g < 0.f) ? g * 1.1f : g / 1.1f;
}
__global__ void __launch_bounds__(256) pen_scatter(const int* __restrict__ ids) {
    const int t = blockIdx.x * 256 + threadIdx.x;
    if (t >= B_ * HIST_) return;
    const int b = t >> 11;
    const int v = ids[t];
    if ((unsigned)v >= (unsigned)V_) return;
    g_logits[(size_t)b * V_ + v] = g_pen[t];
}

// ---------------- K2: per-row top-50 + top-p ----------------
__global__ void __launch_bounds__(1024, 1) select_kernel(float* __restrict__ out,
                                                         int out_size) {
    __shared__ unsigned int hist[8192];
    __shared__ unsigned long long cand[CAP];
    __shared__ unsigned long long sel[50];
    __shared__ int s_cnt, s_tbin;

    const int b = blockIdx.x, tid = threadIdx.x;
    const float* row = g_logits + (size_t)b * V_;

    for (int i = tid; i < 8192; i += 1024) hist[i] = 0u;
    if (tid == 0) s_cnt = 0;
    __syncthreads();

    for (int i = tid; i < V_; i += 1024) {
        const unsigned u = __float_as_uint(row[i]);
        const unsigned key = (u & 0x80000000u) ? ~u : (u | 0x80000000u);
        atomicAdd(&hist[key >> 19], 1u);
    }
    __syncthreads();

    if (tid == 0) {
        unsigned cum = 0;
        int t = 0;
        for (int bin = 8191; bin >= 0; bin--) {
            cum += hist[bin];
            if (cum >= 50u) { t = bin; break; }
        }
        s_tbin = t;
    }
    __syncthreads();

    const unsigned tkey = ((unsigned)s_tbin) << 19;
    for (int i = tid; i < V_; i += 1024) {
        const unsigned u = __float_as_uint(row[i]);
        const unsigned key = (u & 0x80000000u) ? ~u : (u | 0x80000000u);
        if (key >= tkey) {
            const int pos = atomicAdd(&s_cnt, 1);
            if (pos < CAP)
                cand[pos] = ((unsigned long long)key << 32) | (unsigned)(0xffffffffu - i);
        }
    }
    __syncthreads();
    const int cnt = (s_cnt < CAP) ? s_cnt : CAP;

    if (tid < 32) {
        for (int r = 0; r < 50; r++) {
            unsigned long long best = 0ull;
            int bidx = -1;
            for (int i = tid; i < cnt; i += 32)
                if (cand[i] > best) { best = cand[i]; bidx = i; }
#pragma unroll
            for (int off = 16; off >= 1; off >>= 1) {
                const unsigned long long ob = __shfl_xor_sync(0xffffffffu, best, off);
                const int oi = __shfl_xor_sync(0xffffffffu, bidx, off);
                if (ob > best) { best = ob; bidx = oi; }
            }
            if (tid == 0 && bidx >= 0) { sel[r] = best; cand[bidx] = 0ull; }
            __syncwarp();
        }
    }
    __syncthreads();

    if (tid == 0) {
        float vals[50];
        int   tok[50];
        for (int i = 0; i < 50; i++) {
            const unsigned long long k64 = sel[i];
            const unsigned key = (unsigned)(k64 >> 32);
            vals[i] = (key & 0x80000000u) ? __uint_as_float(key ^ 0x80000000u)
                                          : __uint_as_float(~key);
            tok[i] = (int)(0xffffffffu - (unsigned)(k64 & 0xffffffffu));
        }
        const float m = vals[0];
        float e[50], ssum = 0.f;
        for (int i = 0; i < 50; i++) { e[i] = expf(vals[i] - m); ssum += e[i]; }
        float cum = 0.f, filt[50];
        for (int i = 0; i < 50; i++) {
            cum += e[i] / ssum;
            const bool keep = (cum < 0.8f) || (i < 5);
            filt[i] = keep ? vals[i] : -1000.0f;
        }
        float m2 = filt[0];
        for (int i = 1; i < 50; i++) m2 = fmaxf(m2, filt[i]);
        float s2 = 0.f;
        for (int i = 0; i < 50; i++) s2 += expf(filt[i] - m2);
        const int toff = out_size >> 1;
        for (int i = 0; i < 50; i++) {
            out[b * 50 + i] = expf(filt[i] - m2) / s2;
            out[toff + b * 50 + i] = (float)tok[i];
        }
    }
}

// ---------------- launch ----------------
extern "C" void kernel_launch(void* const* d_in, const int* in_sizes, int n_in,
                              void* d_out, int out_size) {
    const int*   ids   = (const int*)d_in[0];
    const float* hs    = (const float*)d_in[1];
    const float* gamma = (const float*)d_in[2];
    const float* beta  = (const float*)d_in[3];
    const float* Wm    = (const float*)d_in[4];

    ln_kernel<<<B_, 256>>>(hs, gamma, beta);
    gemm_kernel<<<V_ / VTILE, 256>>>(Wm);
    pen_gather<<<(B_ * HIST_) / 256, 256>>>(ids);
    pen_scatter<<<(B_ * HIST_) / 256, 256>>>(ids);
    select_kernel<<<B_, 1024>>>((float*)d_out, out_size);
}

// round 6
// speedup vs baseline: 1.6613x; 1.6613x over previous
#include <cuda_runtime.h>
#include <cuda_bf16.h>
#include <cstdint>

#define B_     32
#define H_     2048
#define V_     128000
#define HIST_  2048
#define NT     128          // W rows per CTA
#define KC     64           // K chunk
#define NCHUNK (H_ / KC)    // 32
#define CAP    1024

// ---------------- device scratch ----------------
__device__ __nv_bfloat16 g_ahi[B_ * H_];
__device__ __nv_bfloat16 g_alo[B_ * H_];
__device__ float         g_logits[(size_t)B_ * V_];
__device__ float         g_pen[B_ * HIST_];

// ---------------- helpers ----------------
__device__ __forceinline__ uint32_t smem_u32(const void* p) {
    uint32_t a;
    asm("{ .reg .u64 t; cvta.to.shared.u64 t, %1; cvt.u32.u64 %0, t; }" : "=r"(a) : "l"(p));
    return a;
}
#define SWZ(o) ((o) ^ (((o) >> 3) & 0x70))

__device__ __forceinline__ uint32_t pack_bf16x2(float lo, float hi) {
    uint32_t r;
    asm("cvt.rn.bf16x2.f32 %0, %1, %2;" : "=r"(r) : "f"(hi), "f"(lo));  // hi->upper, lo->lower
    return r;
}
__device__ __forceinline__ void ldmx4(uint32_t* r, uint32_t addr) {
    asm volatile("ldmatrix.sync.aligned.m8n8.x4.shared.b16 {%0,%1,%2,%3}, [%4];"
                 : "=r"(r[0]), "=r"(r[1]), "=r"(r[2]), "=r"(r[3]) : "r"(addr));
}
__device__ __forceinline__ void mma16816(float* d, const uint32_t* a,
                                         uint32_t b0, uint32_t b1) {
    asm volatile(
        "mma.sync.aligned.m16n8k16.row.col.f32.bf16.bf16.f32 "
        "{%0,%1,%2,%3}, {%4,%5,%6,%7}, {%8,%9}, {%0,%1,%2,%3};"
        : "+f"(d[0]), "+f"(d[1]), "+f"(d[2]), "+f"(d[3])
        : "r"(a[0]), "r"(a[1]), "r"(a[2]), "r"(a[3]), "r"(b0), "r"(b1));
}

// ---------------- K0: LayerNorm -> bf16 hi/lo ----------------
__global__ void __launch_bounds__(256) ln_kernel(const float* __restrict__ hs,
                                                 const float* __restrict__ gamma,
                                                 const float* __restrict__ beta) {
    __shared__ float sbuf[8];
    const int b = blockIdx.x, tid = threadIdx.x;
    const float* x = hs + (size_t)b * H_;

    float v[8];
#pragma unroll
    for (int i = 0; i < 8; i++) v[i] = x[i * 256 + tid];

    float s = 0.f;
#pragma unroll
    for (int i = 0; i < 8; i++) s += v[i];
#pragma unroll
    for (int off = 16; off >= 1; off >>= 1) s += __shfl_xor_sync(0xffffffffu, s, off);
    if ((tid & 31) == 0) sbuf[tid >> 5] = s;
    __syncthreads();
    if (tid == 0) {
        float t = 0.f;
        for (int i = 0; i < 8; i++) t += sbuf[i];
        sbuf[0] = t * (1.0f / H_);
    }
    __syncthreads();
    const float mean = sbuf[0];
    __syncthreads();

    float sq = 0.f;
#pragma unroll
    for (int i = 0; i < 8; i++) { float d = v[i] - mean; sq += d * d; }
#pragma unroll
    for (int off = 16; off >= 1; off >>= 1) sq += __shfl_xor_sync(0xffffffffu, sq, off);
    if ((tid & 31) == 0) sbuf[tid >> 5] = sq;
    __syncthreads();
    if (tid == 0) {
        float t = 0.f;
        for (int i = 0; i < 8; i++) t += sbuf[i];
        sbuf[0] = t * (1.0f / H_);
    }
    __syncthreads();
    const float rs = rsqrtf(sbuf[0] + 1e-5f);

#pragma unroll
    for (int i = 0; i < 8; i++) {
        const int k = i * 256 + tid;
        const float h = (v[i] - mean) * rs * gamma[k] + beta[k];
        const __nv_bfloat16 hi = __float2bfloat16(h);
        g_ahi[b * H_ + k] = hi;
        g_alo[b * H_ + k] = __float2bfloat16(h - __bfloat162float(hi));
    }
}

// ---------------- K1: bf16 split GEMM via mma.sync (HMMA) ----------------
// grid = V_/NT = 1000, block = 256 (8 warps). Warp w owns n-slice [w*16, w*16+16).
__global__ void __launch_bounds__(256, 2) gemm_mma(const float* __restrict__ W) {
    __shared__ __align__(1024) char smem[41984];
    // layout: A 0..8191 (64 rows x 128B), Whi 8192..24575, Wlo 24576..40959
    const uint32_t sA  = smem_u32(smem);
    const uint32_t sBH = sA + 8192;
    const uint32_t sBL = sA + 24576;

    const int tid  = threadIdx.x;
    const int lane = tid & 31;
    const int wid  = tid >> 5;
    const int wn   = wid * 16;
    const int v0   = blockIdx.x * NT;

    float d1[4][2][4];      // W_hi x [h_hi; h_lo], m-tiles 0-3
    float d2[2][2][4];      // W_lo x h_hi,        m-tiles 0-1
#pragma unroll
    for (int mt = 0; mt < 4; mt++)
#pragma unroll
        for (int nt = 0; nt < 2; nt++)
#pragma unroll
            for (int i = 0; i < 4; i++) d1[mt][nt][i] = 0.f;
#pragma unroll
    for (int mt = 0; mt < 2; mt++)
#pragma unroll
        for (int nt = 0; nt < 2; nt++)
#pragma unroll
            for (int i = 0; i < 4; i++) d2[mt][nt][i] = 0.f;

    // per-lane ldmatrix addressing components
    const int arow = lane & 15;
    const int koff = (lane & 16) ? 8 : 0;   // bf16 elems

    for (int c = 0; c < NCHUNK; c++) {
        const int k0 = c * KC;
        __syncthreads();

        // stage A: 64 rows x 64 bf16 (rows 0-31 hi, 32-63 lo), 512 x 16B
        for (int i = tid; i < 512; i += 256) {
            const int r = i >> 3, q = i & 7;
            const __nv_bfloat16* src = (r < 32) ? &g_ahi[r * H_ + k0 + q * 8]
                                                : &g_alo[(r - 32) * H_ + k0 + q * 8];
            *reinterpret_cast<uint4*>(smem + SWZ(r * 128 + q * 16)) =
                *reinterpret_cast<const uint4*>(src);
        }
        // stage W: 128 rows x 64 fp32 -> bf16 hi/lo, 2048 x float4
        for (int i = tid; i < 2048; i += 256) {
            const int r = i >> 4, q = i & 15;
            const float4 w = *reinterpret_cast<const float4*>(
                W + (size_t)(v0 + r) * H_ + k0 + q * 4);
            const uint32_t h0 = pack_bf16x2(w.x, w.y);
            const uint32_t h1 = pack_bf16x2(w.z, w.w);
            const float r0 = w.x - __uint_as_float(h0 << 16);
            const float r1 = w.y - __uint_as_float(h0 & 0xFFFF0000u);
            const float r2 = w.z - __uint_as_float(h1 << 16);
            const float r3 = w.w - __uint_as_float(h1 & 0xFFFF0000u);
            const uint32_t bo = SWZ(r * 128 + q * 8);
            *reinterpret_cast<uint2*>(smem + 8192 + bo)  = make_uint2(h0, h1);
            *reinterpret_cast<uint2*>(smem + 24576 + bo) =
                make_uint2(pack_bf16x2(r0, r1), pack_bf16x2(r2, r3));
        }
        __syncthreads();

#pragma unroll
        for (int ks = 0; ks < 4; ks++) {
            const int kc = ks * 16 + koff;            // bf16 col for this lane
            uint32_t a[4][4];
#pragma unroll
            for (int mt = 0; mt < 4; mt++)
                ldmx4(a[mt], sA + SWZ((mt * 16 + arow) * 128 + kc * 2));
            uint32_t bh[4], bl[4];
            ldmx4(bh, sBH + SWZ((wn + arow) * 128 + kc * 2));
            ldmx4(bl, sBL + SWZ((wn + arow) * 128 + kc * 2));

#pragma unroll
            for (int mt = 0; mt < 4; mt++)
#pragma unroll
                for (int nt = 0; nt < 2; nt++)
                    mma16816(d1[mt][nt], a[mt], bh[nt], bh[nt + 2]);
#pragma unroll
            for (int mt = 0; mt < 2; mt++)
#pragma unroll
                for (int nt = 0; nt < 2; nt++)
                    mma16816(d2[mt][nt], a[mt], bl[nt], bl[nt + 2]);
        }
    }

    // epilogue: logits[b][v] = d1[mt][..] (hi) + d1[mt+2][..] (lo) + d2[mt][..]
#pragma unroll
    for (int mt = 0; mt < 2; mt++)
#pragma unroll
        for (int nt = 0; nt < 2; nt++)
#pragma unroll
            for (int hf = 0; hf < 2; hf++) {
                const int b = mt * 16 + (lane >> 2) + hf * 8;
                const int v = v0 + wn + nt * 8 + (lane & 3) * 2;
                const float x0 = d1[mt][nt][hf * 2]     + d1[mt + 2][nt][hf * 2] +
                                 d2[mt][nt][hf * 2];
                const float x1 = d1[mt][nt][hf * 2 + 1] + d1[mt + 2][nt][hf * 2 + 1] +
                                 d2[mt][nt][hf * 2 + 1];
                *reinterpret_cast<float2*>(&g_logits[(size_t)b * V_ + v]) =
                    make_float2(x0, x1);
            }
}

// ---------------- P1/P2: repetition penalty ----------------
__global__ void __launch_bounds__(256) pen_gather(const int* __restrict__ ids) {
    const int t = blockIdx.x * 256 + threadIdx.x;
    if (t >= B_ * HIST_) return;
    const int b = t >> 11;
    const int v = ids[t];
    if ((unsigned)v >= (unsigned)V_) return;
    const float g = g_logits[(size_t)b * V_ + v];
    g_pen[t] = (g < 0.f) ? g * 1.1f : g / 1.1f;
}
__global__ void __launch_bounds__(256) pen_scatter(const int* __restrict__ ids) {
    const int t = blockIdx.x * 256 + threadIdx.x;
    if (t >= B_ * HIST_) return;
    const int b = t >> 11;
    const int v = ids[t];
    if ((unsigned)v >= (unsigned)V_) return;
    g_logits[(size_t)b * V_ + v] = g_pen[t];
}

// ---------------- K2: per-row top-50 + top-p ----------------
__global__ void __launch_bounds__(1024, 1) select_kernel(float* __restrict__ out,
                                                         int out_size) {
    __shared__ unsigned int hist[8192];
    __shared__ unsigned long long cand[CAP];
    __shared__ unsigned long long sel[50];
    __shared__ int s_cnt, s_tbin;

    const int b = blockIdx.x, tid = threadIdx.x;
    const float* row = g_logits + (size_t)b * V_;

    for (int i = tid; i < 8192; i += 1024) hist[i] = 0u;
    if (tid == 0) s_cnt = 0;
    __syncthreads();

    for (int i = tid; i < V_; i += 1024) {
        const unsigned u = __float_as_uint(row[i]);
        const unsigned key = (u & 0x80000000u) ? ~u : (u | 0x80000000u);
        atomicAdd(&hist[key >> 19], 1u);
    }
    __syncthreads();

    if (tid == 0) {
        unsigned cum = 0;
        int t = 0;
        for (int bin = 8191; bin >= 0; bin--) {
            cum += hist[bin];
            if (cum >= 50u) { t = bin; break; }
        }
        s_tbin = t;
    }
    __syncthreads();

    const unsigned tkey = ((unsigned)s_tbin) << 19;
    for (int i = tid; i < V_; i += 1024) {
        const unsigned u = __float_as_uint(row[i]);
        const unsigned key = (u & 0x80000000u) ? ~u : (u | 0x80000000u);
        if (key >= tkey) {
            const int pos = atomicAdd(&s_cnt, 1);
            if (pos < CAP)
                cand[pos] = ((unsigned long long)key << 32) | (unsigned)(0xffffffffu - i);
        }
    }
    __syncthreads();
    const int cnt = (s_cnt < CAP) ? s_cnt : CAP;

    if (tid < 32) {
        for (int r = 0; r < 50; r++) {
            unsigned long long best = 0ull;
            int bidx = -1;
            for (int i = tid; i < cnt; i += 32)
                if (cand[i] > best) { best = cand[i]; bidx = i; }
#pragma unroll
            for (int off = 16; off >= 1; off >>= 1) {
                const unsigned long long ob = __shfl_xor_sync(0xffffffffu, best, off);
                const int oi = __shfl_xor_sync(0xffffffffu, bidx, off);
                if (ob > best) { best = ob; bidx = oi; }
            }
            if (tid == 0 && bidx >= 0) { sel[r] = best; cand[bidx] = 0ull; }
            __syncwarp();
        }
    }
    __syncthreads();

    if (tid == 0) {
        float vals[50];
        int   tok[50];
        for (int i = 0; i < 50; i++) {
            const unsigned long long k64 = sel[i];
            const unsigned key = (unsigned)(k64 >> 32);
            vals[i] = (key & 0x80000000u) ? __uint_as_float(key ^ 0x80000000u)
                                          : __uint_as_float(~key);
            tok[i] = (int)(0xffffffffu - (unsigned)(k64 & 0xffffffffu));
        }
        const float m = vals[0];
        float e[50], ssum = 0.f;
        for (int i = 0; i < 50; i++) { e[i] = expf(vals[i] - m); ssum += e[i]; }
        float cum = 0.f, filt[50];
        for (int i = 0; i < 50; i++) {
            cum += e[i] / ssum;
            const bool keep = (cum < 0.8f) || (i < 5);
            filt[i] = keep ? vals[i] : -1000.0f;
        }
        float m2 = filt[0];
        for (int i = 1; i < 50; i++) m2 = fmaxf(m2, filt[i]);
        float s2 = 0.f;
        for (int i = 0; i < 50; i++) s2 += expf(filt[i] - m2);
        const int toff = out_size >> 1;
        for (int i = 0; i < 50; i++) {
            out[b * 50 + i] = expf(filt[i] - m2) / s2;
            out[toff + b * 50 + i] = (float)tok[i];
        }
    }
}

// ---------------- launch ----------------
extern "C" void kernel_launch(void* const* d_in, const int* in_sizes, int n_in,
                              void* d_out, int out_size) {
    const int*   ids   = (const int*)d_in[0];
    const float* hs    = (const float*)d_in[1];
    const float* gamma = (const float*)d_in[2];
    const float* beta  = (const float*)d_in[3];
    const float* Wm    = (const float*)d_in[4];

    ln_kernel<<<B_, 256>>>(hs, gamma, beta);
    gemm_mma<<<V_ / NT, 256>>>(Wm);
    pen_gather<<<(B_ * HIST_) / 256, 256>>>(ids);
    pen_scatter<<<(B_ * HIST_) / 256, 256>>>(ids);
    select_kernel<<<B_, 1024>>>((float*)d_out, out_size);
}

// round 7
// speedup vs baseline: 2.9149x; 1.7546x over previous
#include <cuda_runtime.h>
#include <cuda_bf16.h>
#include <cstdint>

#define B_     32
#define H_     2048
#define V_     128000
#define HIST_  2048
#define NT     128          // W rows per CTA
#define KC     64           // K chunk
#define NCHUNK (H_ / KC)    // 32
#define CAP    1024

// dynamic SMEM layout (bytes):
//   A buf0 @ 0, A buf1 @ 8192            (64 rows x 128B, SW128-swizzled bf16)
//   W buf0 @ 16384, W buf1 @ 51200       (128 rows x 272B padded fp32)
#define WSTRIDE_F 68                      // floats per padded W row (272B)
#define SMEM_SZ   (16384 + 2 * 34816)     // 86016

// ---------------- device scratch ----------------
__device__ __nv_bfloat16 g_ahi[B_ * H_];
__device__ __nv_bfloat16 g_alo[B_ * H_];
__device__ float         g_logits[(size_t)B_ * V_];
__device__ float         g_pen[B_ * HIST_];

// ---------------- helpers ----------------
__device__ __forceinline__ uint32_t smem_u32(const void* p) {
    uint32_t a;
    asm("{ .reg .u64 t; cvta.to.shared.u64 t, %1; cvt.u32.u64 %0, t; }" : "=r"(a) : "l"(p));
    return a;
}
#define SWZ(o) ((o) ^ (((o) >> 3) & 0x70))

#define CP16(dst, src) \
    asm volatile("cp.async.cg.shared.global [%0], [%1], 16;" :: "r"(dst), "l"(src))
#define CP_COMMIT() asm volatile("cp.async.commit_group;" ::: "memory")
#define CP_WAIT1()  asm volatile("cp.async.wait_group 1;" ::: "memory")

__device__ __forceinline__ uint32_t pack_bf16x2(float lo, float hi) {
    uint32_t r;
    asm("cvt.rn.bf16x2.f32 %0, %1, %2;" : "=r"(r) : "f"(hi), "f"(lo));  // hi->upper
    return r;
}
__device__ __forceinline__ void ldmx4(uint32_t* r, uint32_t addr) {
    asm volatile("ldmatrix.sync.aligned.m8n8.x4.shared.b16 {%0,%1,%2,%3}, [%4];"
                 : "=r"(r[0]), "=r"(r[1]), "=r"(r[2]), "=r"(r[3]) : "r"(addr));
}
__device__ __forceinline__ void mma16816(float* d, const uint32_t* a,
                                         uint32_t b0, uint32_t b1) {
    asm volatile(
        "mma.sync.aligned.m16n8k16.row.col.f32.bf16.bf16.f32 "
        "{%0,%1,%2,%3}, {%4,%5,%6,%7}, {%8,%9}, {%0,%1,%2,%3};"
        : "+f"(d[0]), "+f"(d[1]), "+f"(d[2]), "+f"(d[3])
        : "r"(a[0]), "r"(a[1]), "r"(a[2]), "r"(a[3]), "r"(b0), "r"(b1));
}

// ---------------- K0: LayerNorm -> bf16 hi/lo ----------------
__global__ void __launch_bounds__(256) ln_kernel(const float* __restrict__ hs,
                                                 const float* __restrict__ gamma,
                                                 const float* __restrict__ beta) {
    __shared__ float sbuf[8];
    const int b = blockIdx.x, tid = threadIdx.x;
    const float* x = hs + (size_t)b * H_;

    float v[8];
#pragma unroll
    for (int i = 0; i < 8; i++) v[i] = x[i * 256 + tid];

    float s = 0.f;
#pragma unroll
    for (int i = 0; i < 8; i++) s += v[i];
#pragma unroll
    for (int off = 16; off >= 1; off >>= 1) s += __shfl_xor_sync(0xffffffffu, s, off);
    if ((tid & 31) == 0) sbuf[tid >> 5] = s;
    __syncthreads();
    if (tid == 0) {
        float t = 0.f;
        for (int i = 0; i < 8; i++) t += sbuf[i];
        sbuf[0] = t * (1.0f / H_);
    }
    __syncthreads();
    const float mean = sbuf[0];
    __syncthreads();

    float sq = 0.f;
#pragma unroll
    for (int i = 0; i < 8; i++) { float d = v[i] - mean; sq += d * d; }
#pragma unroll
    for (int off = 16; off >= 1; off >>= 1) sq += __shfl_xor_sync(0xffffffffu, sq, off);
    if ((tid & 31) == 0) sbuf[tid >> 5] = sq;
    __syncthreads();
    if (tid == 0) {
        float t = 0.f;
        for (int i = 0; i < 8; i++) t += sbuf[i];
        sbuf[0] = t * (1.0f / H_);
    }
    __syncthreads();
    const float rs = rsqrtf(sbuf[0] + 1e-5f);

#pragma unroll
    for (int i = 0; i < 8; i++) {
        const int k = i * 256 + tid;
        const float h = (v[i] - mean) * rs * gamma[k] + beta[k];
        const __nv_bfloat16 hi = __float2bfloat16(h);
        g_ahi[b * H_ + k] = hi;
        g_alo[b * H_ + k] = __float2bfloat16(h - __bfloat162float(hi));
    }
}

// ---------------- K1: pipelined bf16 split GEMM (cp.async + HMMA) ----------------
__global__ void __launch_bounds__(256, 2) gemm_mma(const float* __restrict__ W) {
    extern __shared__ __align__(16) char smem[];
    const uint32_t sb = smem_u32(smem);

    const int tid  = threadIdx.x;
    const int lane = tid & 31;
    const int wid  = tid >> 5;
    const int wn   = wid * 16;
    const int v0   = blockIdx.x * NT;

    float d1[4][2][4];      // W_hi x [h_hi; h_lo], m-tiles 0-3
    float d2[2][2][4];      // W_lo x h_hi,        m-tiles 0-1
#pragma unroll
    for (int mt = 0; mt < 4; mt++)
#pragma unroll
        for (int nt = 0; nt < 2; nt++)
#pragma unroll
            for (int i = 0; i < 4; i++) d1[mt][nt][i] = 0.f;
#pragma unroll
    for (int mt = 0; mt < 2; mt++)
#pragma unroll
        for (int nt = 0; nt < 2; nt++)
#pragma unroll
            for (int i = 0; i < 4; i++) d2[mt][nt][i] = 0.f;

    const int arow = lane & 15;
    const int koff = (lane & 16) ? 8 : 0;
    const int brow = wn + (lane >> 2);          // W row for B frags (nt adds 8)
    const int bk   = (lane & 3) * 2;            // k offset within kstep

    // ---- staging lambda ----
    auto stage = [&](int c) {
        const int buf = c & 1;
        const int k0  = c * KC;
        const uint32_t ab = sb + buf * 8192;
        const uint32_t wb = sb + 16384 + buf * 34816;
        // A: 64 rows x 128B, 512 x 16B, swizzled
#pragma unroll
        for (int i = tid; i < 512; i += 256) {
            const int r = i >> 3, q = i & 7;
            const void* src = (r < 32) ? (const void*)&g_ahi[r * H_ + k0 + q * 8]
                                       : (const void*)&g_alo[(r - 32) * H_ + k0 + q * 8];
            CP16(ab + SWZ(r * 128 + q * 16), src);
        }
        // W: 128 rows x 64 fp32, padded stride
#pragma unroll
        for (int i = tid; i < 2048; i += 256) {
            const int r = i >> 4, q = i & 15;
            CP16(wb + r * 272 + q * 16, W + (size_t)(v0 + r) * H_ + k0 + q * 4);
        }
    };

    stage(0);
    CP_COMMIT();

    for (int c = 0; c < NCHUNK; c++) {
        if (c + 1 < NCHUNK) stage(c + 1);
        CP_COMMIT();
        CP_WAIT1();
        __syncthreads();

        const int buf = c & 1;
        const uint32_t sA = sb + buf * 8192;
        const float* Wb = reinterpret_cast<const float*>(smem + 16384 + buf * 34816);

#pragma unroll
        for (int ks = 0; ks < 4; ks++) {
            const int kc = ks * 16 + koff;
            uint32_t a[4][4];
#pragma unroll
            for (int mt = 0; mt < 4; mt++)
                ldmx4(a[mt], sA + SWZ((mt * 16 + arow) * 128 + kc * 2));

#pragma unroll
            for (int nt = 0; nt < 2; nt++) {
                const float* wr = Wb + (brow + nt * 8) * WSTRIDE_F + ks * 16 + bk;
                const float2 w0 = *reinterpret_cast<const float2*>(wr);
                const float2 w1 = *reinterpret_cast<const float2*>(wr + 8);

                const uint32_t bh0 = pack_bf16x2(w0.x, w0.y);
                const uint32_t bh1 = pack_bf16x2(w1.x, w1.y);
                const float r0 = w0.x - __uint_as_float(bh0 << 16);
                const float r1 = w0.y - __uint_as_float(bh0 & 0xFFFF0000u);
                const float r2 = w1.x - __uint_as_float(bh1 << 16);
                const float r3 = w1.y - __uint_as_float(bh1 & 0xFFFF0000u);
                const uint32_t bl0 = pack_bf16x2(r0, r1);
                const uint32_t bl1 = pack_bf16x2(r2, r3);

#pragma unroll
                for (int mt = 0; mt < 4; mt++)
                    mma16816(d1[mt][nt], a[mt], bh0, bh1);
#pragma unroll
                for (int mt = 0; mt < 2; mt++)
                    mma16816(d2[mt][nt], a[mt], bl0, bl1);
            }
        }
        __syncthreads();
    }

    // epilogue: logits[b][v] = hi-hi + hi-lo(A) + lo(W)-hi
#pragma unroll
    for (int mt = 0; mt < 2; mt++)
#pragma unroll
        for (int nt = 0; nt < 2; nt++)
#pragma unroll
            for (int hf = 0; hf < 2; hf++) {
                const int b = mt * 16 + (lane >> 2) + hf * 8;
                const int v = v0 + wn + nt * 8 + (lane & 3) * 2;
                const float x0 = d1[mt][nt][hf * 2]     + d1[mt + 2][nt][hf * 2] +
                                 d2[mt][nt][hf * 2];
                const float x1 = d1[mt][nt][hf * 2 + 1] + d1[mt + 2][nt][hf * 2 + 1] +
                                 d2[mt][nt][hf * 2 + 1];
                *reinterpret_cast<float2*>(&g_logits[(size_t)b * V_ + v]) =
                    make_float2(x0, x1);
            }
}

// ---------------- P1/P2: repetition penalty ----------------
__global__ void __launch_bounds__(256) pen_gather(const int* __restrict__ ids) {
    const int t = blockIdx.x * 256 + threadIdx.x;
    if (t >= B_ * HIST_) return;
    const int b = t >> 11;
    const int v = ids[t];
    if ((unsigned)v >= (unsigned)V_) return;
    const float g = g_logits[(size_t)b * V_ + v];
    g_pen[t] = (g < 0.f) ? g * 1.1f : g / 1.1f;
}
__global__ void __launch_bounds__(256) pen_scatter(const int* __restrict__ ids) {
    const int t = blockIdx.x * 256 + threadIdx.x;
    if (t >= B_ * HIST_) return;
    const int b = t >> 11;
    const int v = ids[t];
    if ((unsigned)v >= (unsigned)V_) return;
    g_logits[(size_t)b * V_ + v] = g_pen[t];
}

// ---------------- K2: per-row top-50 + top-p ----------------
__global__ void __launch_bounds__(1024, 1) select_kernel(float* __restrict__ out,
                                                         int out_size) {
    __shared__ unsigned int hist[8192];
    __shared__ unsigned long long cand[CAP];
    __shared__ unsigned long long sel[50];
    __shared__ int s_cnt, s_tbin;

    const int b = blockIdx.x, tid = threadIdx.x;
    const float* row = g_logits + (size_t)b * V_;

    for (int i = tid; i < 8192; i += 1024) hist[i] = 0u;
    if (tid == 0) s_cnt = 0;
    __syncthreads();

    for (int i = tid; i < V_; i += 1024) {
        const unsigned u = __float_as_uint(row[i]);
        const unsigned key = (u & 0x80000000u) ? ~u : (u | 0x80000000u);
        atomicAdd(&hist[key >> 19], 1u);
    }
    __syncthreads();

    if (tid == 0) {
        unsigned cum = 0;
        int t = 0;
        for (int bin = 8191; bin >= 0; bin--) {
            cum += hist[bin];
            if (cum >= 50u) { t = bin; break; }
        }
        s_tbin = t;
    }
    __syncthreads();

    const unsigned tkey = ((unsigned)s_tbin) << 19;
    for (int i = tid; i < V_; i += 1024) {
        const unsigned u = __float_as_uint(row[i]);
        const unsigned key = (u & 0x80000000u) ? ~u : (u | 0x80000000u);
        if (key >= tkey) {
            const int pos = atomicAdd(&s_cnt, 1);
            if (pos < CAP)
                cand[pos] = ((unsigned long long)key << 32) | (unsigned)(0xffffffffu - i);
        }
    }
    __syncthreads();
    const int cnt = (s_cnt < CAP) ? s_cnt : CAP;

    if (tid < 32) {
        for (int r = 0; r < 50; r++) {
            unsigned long long best = 0ull;
            int bidx = -1;
            for (int i = tid; i < cnt; i += 32)
                if (cand[i] > best) { best = cand[i]; bidx = i; }
#pragma unroll
            for (int off = 16; off >= 1; off >>= 1) {
                const unsigned long long ob = __shfl_xor_sync(0xffffffffu, best, off);
                const int oi = __shfl_xor_sync(0xffffffffu, bidx, off);
                if (ob > best) { best = ob; bidx = oi; }
            }
            if (tid == 0 && bidx >= 0) { sel[r] = best; cand[bidx] = 0ull; }
            __syncwarp();
        }
    }
    __syncthreads();

    if (tid == 0) {
        float vals[50];
        int   tok[50];
        for (int i = 0; i < 50; i++) {
            const unsigned long long k64 = sel[i];
            const unsigned key = (unsigned)(k64 >> 32);
            vals[i] = (key & 0x80000000u) ? __uint_as_float(key ^ 0x80000000u)
                                          : __uint_as_float(~key);
            tok[i] = (int)(0xffffffffu - (unsigned)(k64 & 0xffffffffu));
        }
        const float m = vals[0];
        float e[50], ssum = 0.f;
        for (int i = 0; i < 50; i++) { e[i] = expf(vals[i] - m); ssum += e[i]; }
        float cum = 0.f, filt[50];
        for (int i = 0; i < 50; i++) {
            cum += e[i] / ssum;
            const bool keep = (cum < 0.8f) || (i < 5);
            filt[i] = keep ? vals[i] : -1000.0f;
        }
        float m2 = filt[0];
        for (int i = 1; i < 50; i++) m2 = fmaxf(m2, filt[i]);
        float s2 = 0.f;
        for (int i = 0; i < 50; i++) s2 += expf(filt[i] - m2);
        const int toff = out_size >> 1;
        for (int i = 0; i < 50; i++) {
            out[b * 50 + i] = expf(filt[i] - m2) / s2;
            out[toff + b * 50 + i] = (float)tok[i];
        }
    }
}

// ---------------- launch ----------------
extern "C" void kernel_launch(void* const* d_in, const int* in_sizes, int n_in,
                              void* d_out, int out_size) {
    const int*   ids   = (const int*)d_in[0];
    const float* hs    = (const float*)d_in[1];
    const float* gamma = (const float*)d_in[2];
    const float* beta  = (const float*)d_in[3];
    const float* Wm    = (const float*)d_in[4];

    cudaFuncSetAttribute(gemm_mma, cudaFuncAttributeMaxDynamicSharedMemorySize, SMEM_SZ);

    ln_kernel<<<B_, 256>>>(hs, gamma, beta);
    gemm_mma<<<V_ / NT, 256, SMEM_SZ>>>(Wm);
    pen_gather<<<(B_ * HIST_) / 256, 256>>>(ids);
    pen_scatter<<<(B_ * HIST_) / 256, 256>>>(ids);
    select_kernel<<<B_, 1024>>>((float*)d_out, out_size);
}